// round 5
// baseline (speedup 1.0000x reference)
#include <cuda_runtime.h>
#include <math.h>
#include <stdint.h>
#include <string.h>

#define T_STEPS 1024
#define BATCH   64
#define VDIM    256
#define HIDDEN  512
#define CPB     64                 // columns per CTA
#define BG      4                  // batches per group (= per cluster)
#define CBLKS   (HIDDEN / CPB)     // 8 CTAs per cluster
#define GROUPS  (BATCH / BG)       // 16 clusters
#define NB      (CBLKS * GROUPS)   // 128 CTAs
#define RT      256
#define WPAD    516                // Wh smem row stride (floats)
#define HPAD    520                // h smem row stride (floats)
#define REC_SMEM ((CPB * WPAD + 2 * BG * HPAD) * 4)   // ~145 KB

// Scratch (device globals: allocation APIs are forbidden)
__device__ float g_P [(size_t)T_STEPS * BATCH * HIDDEN];
__device__ float g_S0[(size_t)T_STEPS * BATCH * HIDDEN];

// packed f32x2 fma: acc.lo += w.lo*h.lo ; acc.hi += w.hi*h.hi
#define FMA2(acc, w, h) \
    asm("fma.rn.f32x2 %0, %1, %2, %0;" : "+l"(acc) : "l"(w), "l"(h))

// ---------------------------------------------------------------------------
// GEMM: C[m][n] = sum_k A[m][k]*W[n*ldw+k] + bias[n], C row stride = HIDDEN
// ---------------------------------------------------------------------------
__global__ __launch_bounds__(256) void gemm_awt(
    const float* __restrict__ A, const float* __restrict__ W,
    const float* __restrict__ bias, float* __restrict__ C,
    int K, int ldw)
{
    __shared__ float As[8][128];
    __shared__ float Ws[8][128];

    const int tid = threadIdx.x;
    const int m0 = blockIdx.y * 128;
    const int n0 = blockIdx.x * 128;
    const int tx = tid & 15;
    const int ty = tid >> 4;
    const int rowL = tid >> 1;
    const int colL = (tid & 1) * 4;

    const float* Ag = A + (size_t)(m0 + rowL) * K + colL;
    const float* Wg = W + (size_t)(n0 + rowL) * ldw + colL;

    float acc[8][8];
#pragma unroll
    for (int i = 0; i < 8; ++i)
#pragma unroll
        for (int j = 0; j < 8; ++j) acc[i][j] = 0.f;

    float4 av = *(const float4*)(Ag);
    float4 wv = *(const float4*)(Wg);

    for (int k0 = 0; k0 < K; k0 += 8) {
        __syncthreads();
        As[colL + 0][rowL] = av.x; As[colL + 1][rowL] = av.y;
        As[colL + 2][rowL] = av.z; As[colL + 3][rowL] = av.w;
        Ws[colL + 0][rowL] = wv.x; Ws[colL + 1][rowL] = wv.y;
        Ws[colL + 2][rowL] = wv.z; Ws[colL + 3][rowL] = wv.w;
        __syncthreads();
        if (k0 + 8 < K) {
            av = *(const float4*)(Ag + k0 + 8);
            wv = *(const float4*)(Wg + k0 + 8);
        }
#pragma unroll
        for (int k = 0; k < 8; ++k) {
            float a[8], b[8];
#pragma unroll
            for (int i = 0; i < 8; ++i) a[i] = As[k][ty * 8 + i];
#pragma unroll
            for (int j = 0; j < 8; ++j) b[j] = Ws[k][tx * 8 + j];
#pragma unroll
            for (int i = 0; i < 8; ++i)
#pragma unroll
                for (int j = 0; j < 8; ++j)
                    acc[i][j] += a[i] * b[j];
        }
    }

    float bn[8];
#pragma unroll
    for (int j = 0; j < 8; ++j) bn[j] = bias[n0 + tx * 8 + j];

    float* Cp = C + (size_t)(m0 + ty * 8) * HIDDEN + n0 + tx * 8;
#pragma unroll
    for (int i = 0; i < 8; ++i) {
        float4 v0, v1;
        v0.x = acc[i][0] + bn[0]; v0.y = acc[i][1] + bn[1];
        v0.z = acc[i][2] + bn[2]; v0.w = acc[i][3] + bn[3];
        v1.x = acc[i][4] + bn[4]; v1.y = acc[i][5] + bn[5];
        v1.z = acc[i][6] + bn[6]; v1.w = acc[i][7] + bn[7];
        *(float4*)(Cp + (size_t)i * HIDDEN)     = v0;
        *(float4*)(Cp + (size_t)i * HIDDEN + 4) = v1;
    }
}

// ---------------------------------------------------------------------------
// Persistent recurrence, cluster version.
//   cluster = 8 CTAs = one batch group (4 batches); CTA r owns cols [64r,64r+64).
//   Wh slice resident in smem. h exchanged via DSMEM stores to all 8 peers;
//   step barrier = barrier.cluster (release orders the DSMEM stores).
// ---------------------------------------------------------------------------
__global__ __launch_bounds__(RT, 1) __cluster_dims__(CBLKS, 1, 1)
void rnn_rec(
    const float* __restrict__ P,
    const float* __restrict__ Wfull, int ldw, int koff,
    const float* __restrict__ h0,
    float* __restrict__ states,
    float* __restrict__ last)
{
    extern __shared__ float sh[];
    float* Whs = sh;                       // [64][WPAD]
    float* Hsb = sh + CPB * WPAD;          // [2][4][HPAD]

    const int tid  = threadIdx.x;
    const int cblk = blockIdx.x & (CBLKS - 1);   // == cluster rank
    const int grp  = blockIdx.x >> 3;
    const int j0   = cblk * CPB;
    const int bl   = tid & (BG - 1);       // 0..3 local batch
    const int jl   = tid >> 2;             // 0..63 local column
    const int j    = j0 + jl;
    const int b    = grp * BG + bl;

    // Load this CTA's Wh rows (64 x 512) into padded smem.
    for (int idx = tid; idx < CPB * HIDDEN; idx += RT) {
        int r = idx >> 9, k = idx & 511;
        Whs[r * WPAD + k] = Wfull[(size_t)(j0 + r) * ldw + koff + k];
    }
    // Stage h0 for our 4 batches into buffer 0 (full 512-vector per batch).
    for (int i = tid; i < BG * HIDDEN; i += RT) {
        int bb = i >> 9, k = i & 511;
        Hsb[bb * HPAD + k] = h0[(size_t)(grp * BG + bb) * HIDDEN + k];
    }
    __syncthreads();
    asm volatile("barrier.cluster.arrive.aligned;" ::: "memory");
    asm volatile("barrier.cluster.wait.aligned;"   ::: "memory");

    const longlong2* w2 = (const longlong2*)(Whs + jl * WPAD);

    for (int t = 0; t < T_STEPS; ++t) {
        const int cur = t & 1, nxt = cur ^ 1;
        float p = P[((size_t)t * BATCH + b) * HIDDEN + j];   // latency hidden by dot

        const longlong2* h2 = (const longlong2*)(Hsb + (cur * BG + bl) * HPAD);

        long long a0 = 0, a1 = 0, a2 = 0, a3 = 0;
#pragma unroll 16
        for (int i = 0; i < HIDDEN / 4; ++i) {       // 128 float4 pairs
            longlong2 w = w2[i];
            longlong2 h = h2[i];
            if (i & 1) { FMA2(a2, w.x, h.x); FMA2(a3, w.y, h.y); }
            else       { FMA2(a0, w.x, h.x); FMA2(a1, w.y, h.y); }
        }
        float2 f0 = *reinterpret_cast<float2*>(&a0);
        float2 f1 = *reinterpret_cast<float2*>(&a1);
        float2 f2 = *reinterpret_cast<float2*>(&a2);
        float2 f3 = *reinterpret_cast<float2*>(&a3);
        float acc = ((f0.x + f0.y) + (f1.x + f1.y)) +
                    ((f2.x + f2.y) + (f3.x + f3.y));
        float hv = tanhf(p + acc);

        // Scatter hv into every cluster CTA's smem: Hsb[nxt][bl][j].
        {
            unsigned loc = (unsigned)__cvta_generic_to_shared(
                               Hsb + (nxt * BG + bl) * HPAD + j);
#pragma unroll
            for (int r = 0; r < CBLKS; ++r) {
                unsigned pa;
                asm("mapa.shared::cluster.u32 %0, %1, %2;"
                    : "=r"(pa) : "r"(loc), "r"(r));
                asm volatile("st.shared::cluster.f32 [%0], %1;"
                             :: "r"(pa), "f"(hv) : "memory");
            }
        }

        states[((size_t)t * BATCH + b) * HIDDEN + j] = hv;
        if (t == T_STEPS - 1) last[(size_t)b * HIDDEN + j] = hv;

        // Cluster barrier: orders DSMEM stores, syncs the 8 CTAs of the group.
        asm volatile("barrier.cluster.arrive.aligned;" ::: "memory");
        asm volatile("barrier.cluster.wait.aligned;"   ::: "memory");
    }
}

// ---------------------------------------------------------------------------
extern "C" void kernel_launch(void* const* d_in, const int* in_sizes, int n_in,
                              void* d_out, int out_size)
{
    (void)in_sizes; (void)n_in; (void)out_size;
    const float* inputs = (const float*)d_in[0];
    const float* H      = (const float*)d_in[1];
    const float* W_net  = (const float*)d_in[2];
    const float* b_net  = (const float*)d_in[3];
    const float* W_deep = (const float*)d_in[4];
    const float* b_deep = (const float*)d_in[5];

    float* out     = (float*)d_out;
    float* states1 = out;
    float* lasts   = out + (size_t)T_STEPS * BATCH * HIDDEN;

    float *P, *S0;
    cudaGetSymbolAddress((void**)&P,  g_P);
    cudaGetSymbolAddress((void**)&S0, g_S0);

    cudaFuncSetAttribute(rnn_rec, cudaFuncAttributeMaxDynamicSharedMemorySize, REC_SMEM);

    dim3 ggrid(HIDDEN / 128, (T_STEPS * BATCH) / 128);

    gemm_awt<<<ggrid, 256>>>(inputs, W_net, b_net, P, VDIM, VDIM + HIDDEN);
    rnn_rec<<<NB, RT, REC_SMEM>>>(P, W_net, VDIM + HIDDEN, VDIM, H, S0, lasts);

    gemm_awt<<<ggrid, 256>>>(S0, W_deep, b_deep, P, HIDDEN, 2 * HIDDEN);
    rnn_rec<<<NB, RT, REC_SMEM>>>(P, W_deep, 2 * HIDDEN, HIDDEN,
                                  H + BATCH * HIDDEN, states1,
                                  lasts + BATCH * HIDDEN);
}